// round 3
// baseline (speedup 1.0000x reference)
#include <cuda_runtime.h>
#include <cstdint>
#include <math.h>

#define BB 2
#define LL 256
#define HH 512
#define NHH 8
#define DHH 64
#define MM (BB*LL)   // 512

// ---------------- device scratch (no allocs allowed) ----------------
__device__ float g_qt [BB*NHH*LL*DHH];   // q_t[b,n,l,d]
__device__ float g_ktT[BB*NHH*DHH*LL];   // k transposed [b,n,d,l]
__device__ float g_vt [BB*NHH*LL*DHH];   // v_t[b,n,l,d]
__device__ float g_w2 [BB*LL*NHH*HH];    // W2[b,q,n,h]
__device__ float g_pre[BB*LL*HH];        // pre-output [b,q, n*64+d]

// ---------------- f32x2 helpers ----------------
__device__ __forceinline__ unsigned long long fma_f32x2(unsigned long long a,
                                                        unsigned long long b,
                                                        unsigned long long c) {
    unsigned long long d;
    asm("fma.rn.f32x2 %0, %1, %2, %3;" : "=l"(d) : "l"(a), "l"(b), "l"(c));
    return d;
}
__device__ __forceinline__ unsigned long long pack2(float x, float y) {
    unsigned long long r;
    asm("mov.b64 %0, {%1, %2};" : "=l"(r) : "f"(x), "f"(y));
    return r;
}
__device__ __forceinline__ float2 unpack2(unsigned long long v) {
    float2 r;
    asm("mov.b64 {%0, %1}, %2;" : "=f"(r.x), "=f"(r.y) : "l"(v));
    return r;
}

// ---------------- NT GEMM: C[m,c] = sum_k X[m,k]*W[c,k] + bias[c] ----------------
// z = 0: query@Wq -> g_qt     z = 1: key@Wk -> g_ktT (transposed)
// z = 2: value@Wv -> g_vt     z = 3: g_pre@Wf -> out_final
__global__ __launch_bounds__(256) void gemm_nt_kernel(
    int zbase,
    const float* __restrict__ key, const float* __restrict__ query, const float* __restrict__ value,
    const float* __restrict__ Wk, const float* __restrict__ bk,
    const float* __restrict__ Wq, const float* __restrict__ bq,
    const float* __restrict__ Wv, const float* __restrict__ bv,
    const float* __restrict__ Wf, const float* __restrict__ bf,
    float* __restrict__ out_final)
{
    int z = zbase + blockIdx.z;
    const float* X; const float* W; const float* bias;
    if (z == 0)      { X = query;  W = Wq; bias = bq; }
    else if (z == 1) { X = key;    W = Wk; bias = bk; }
    else if (z == 2) { X = value;  W = Wv; bias = bv; }
    else             { X = g_pre;  W = Wf; bias = bf; }

    __shared__ float As[16][68];
    __shared__ float Bs[16][68];

    int tid = threadIdx.x;
    int tx = tid & 15, ty = tid >> 4;      // tx -> n dir, ty -> m dir
    int m0 = blockIdx.y * 64, n0 = blockIdx.x * 64;
    int lrow = tid >> 2;                   // 0..63
    int lk4  = (tid & 3) * 4;              // 0,4,8,12

    float acc[4][4];
#pragma unroll
    for (int i = 0; i < 4; i++)
#pragma unroll
        for (int j = 0; j < 4; j++) acc[i][j] = 0.f;

    for (int ks = 0; ks < HH; ks += 16) {
        float4 a  = *(const float4*)&X[(m0 + lrow) * HH + ks + lk4];
        float4 wv = *(const float4*)&W[(n0 + lrow) * HH + ks + lk4];
        As[lk4 + 0][lrow] = a.x;  As[lk4 + 1][lrow] = a.y;
        As[lk4 + 2][lrow] = a.z;  As[lk4 + 3][lrow] = a.w;
        Bs[lk4 + 0][lrow] = wv.x; Bs[lk4 + 1][lrow] = wv.y;
        Bs[lk4 + 2][lrow] = wv.z; Bs[lk4 + 3][lrow] = wv.w;
        __syncthreads();
#pragma unroll
        for (int kk = 0; kk < 16; kk++) {
            float4 av  = *(const float4*)&As[kk][ty * 4];
            float4 bv4 = *(const float4*)&Bs[kk][tx * 4];
            acc[0][0] += av.x * bv4.x; acc[0][1] += av.x * bv4.y;
            acc[0][2] += av.x * bv4.z; acc[0][3] += av.x * bv4.w;
            acc[1][0] += av.y * bv4.x; acc[1][1] += av.y * bv4.y;
            acc[1][2] += av.y * bv4.z; acc[1][3] += av.y * bv4.w;
            acc[2][0] += av.z * bv4.x; acc[2][1] += av.z * bv4.y;
            acc[2][2] += av.z * bv4.z; acc[2][3] += av.z * bv4.w;
            acc[3][0] += av.w * bv4.x; acc[3][1] += av.w * bv4.y;
            acc[3][2] += av.w * bv4.z; acc[3][3] += av.w * bv4.w;
        }
        __syncthreads();
    }

#pragma unroll
    for (int i = 0; i < 4; i++) {
#pragma unroll
        for (int j = 0; j < 4; j++) {
            int m = m0 + ty * 4 + i;   // = b*256 + l
            int c = n0 + tx * 4 + j;   // = n*64 + d
            float v = acc[i][j] + bias[c];
            int b_ = m >> 8, l_ = m & 255, n_ = c >> 6, d_ = c & 63;
            if (z == 0)      g_qt [((b_ * NHH + n_) * LL + l_) * DHH + d_] = v;
            else if (z == 1) g_ktT[((b_ * NHH + n_) * DHH + d_) * LL + l_] = v;
            else if (z == 2) g_vt [((b_ * NHH + n_) * LL + l_) * DHH + d_] = v;
            else             out_final[m * HH + c] = v;
        }
    }
}

// ---------------- W2[b,q,n,h] = sum_d (q_t[b,n,q,d]+v_bias[n,d]) * Wr[n*64+d, h] ----------------
__global__ __launch_bounds__(256) void w2_kernel(const float* __restrict__ Wr,
                                                 const float* __restrict__ v_bias)
{
    int n  = blockIdx.z;
    int m0 = blockIdx.y * 64, h0 = blockIdx.x * 64;

    __shared__ float As[16][68];   // As[d_local][m]
    __shared__ float Bs[16][68];   // Bs[d_local][h]

    int tid = threadIdx.x;
    int tx = tid & 15, ty = tid >> 4;
    int lrow = tid >> 2, lk4 = (tid & 3) * 4;   // A loader: 64 m rows x 16 d
    int brow = tid >> 4, bh4 = (tid & 15) * 4;  // B loader: 16 d rows x 64 h

    float acc[4][4];
#pragma unroll
    for (int i = 0; i < 4; i++)
#pragma unroll
        for (int j = 0; j < 4; j++) acc[i][j] = 0.f;

    for (int ks = 0; ks < DHH; ks += 16) {
        int m = m0 + lrow; int b_ = m >> 8, q_ = m & 255;
        float4 a  = *(const float4*)&g_qt[((b_ * NHH + n) * LL + q_) * DHH + ks + lk4];
        float4 vb = *(const float4*)&v_bias[n * DHH + ks + lk4];
        a.x += vb.x; a.y += vb.y; a.z += vb.z; a.w += vb.w;
        As[lk4 + 0][lrow] = a.x; As[lk4 + 1][lrow] = a.y;
        As[lk4 + 2][lrow] = a.z; As[lk4 + 3][lrow] = a.w;

        float4 wv = *(const float4*)&Wr[(n * DHH + ks + brow) * HH + h0 + bh4];
        *(float4*)&Bs[brow][bh4] = wv;
        __syncthreads();
#pragma unroll
        for (int kk = 0; kk < 16; kk++) {
            float4 av  = *(const float4*)&As[kk][ty * 4];
            float4 bv4 = *(const float4*)&Bs[kk][tx * 4];
            acc[0][0] += av.x * bv4.x; acc[0][1] += av.x * bv4.y;
            acc[0][2] += av.x * bv4.z; acc[0][3] += av.x * bv4.w;
            acc[1][0] += av.y * bv4.x; acc[1][1] += av.y * bv4.y;
            acc[1][2] += av.y * bv4.z; acc[1][3] += av.y * bv4.w;
            acc[2][0] += av.z * bv4.x; acc[2][1] += av.z * bv4.y;
            acc[2][2] += av.z * bv4.z; acc[2][3] += av.z * bv4.w;
            acc[3][0] += av.w * bv4.x; acc[3][1] += av.w * bv4.y;
            acc[3][2] += av.w * bv4.z; acc[3][3] += av.w * bv4.w;
        }
        __syncthreads();
    }

#pragma unroll
    for (int i = 0; i < 4; i++) {
#pragma unroll
        for (int j = 0; j < 4; j++) {
            int m = m0 + ty * 4 + i;
            int h = h0 + tx * 4 + j;
            int b_ = m >> 8, q_ = m & 255;
            g_w2[((size_t)(b_ * LL + q_) * NHH + n) * HH + h] = acc[i][j];
        }
    }
}

// ---------------- fused attention: A_C + B_D + mask + softmax + attn@V ----------------
// one block per (b,q); 256 threads = 8 warps
__global__ __launch_bounds__(256, 1) void attn_kernel(
    const float* __restrict__ rel,
    const float* __restrict__ u_bias,
    const int*   __restrict__ seq_len,
    const int*   __restrict__ lex_num)
{
    int q = blockIdx.x, b = blockIdx.y;
    int tid = threadIdx.x;
    int w = tid >> 5, lane = tid & 31;

    __shared__ float squ[NHH][DHH];   // q + u_bias
    __shared__ float ss[NHH][LL];     // scores -> attn

    // phase 0: load q+u into smem
    {
        int i = tid * 2;                 // flat n*64+d, d even
        int n = i >> 6, d = i & 63;
        float2 t = *(const float2*)&g_qt[((b * NHH + n) * LL + q) * DHH + d];
        float2 u = *(const float2*)&u_bias[i];
        float* sp = &squ[0][0];
        sp[i]     = t.x + u.x;
        sp[i + 1] = t.y + u.y;
    }
    __syncthreads();

    // phase 1: A_C — warp w handles head n=w, lane owns 8 consecutive k
    {
        int n = w;
        float acck[8] = {0.f, 0.f, 0.f, 0.f, 0.f, 0.f, 0.f, 0.f};
        const float* ktp = g_ktT + (size_t)(b * NHH + n) * DHH * LL + lane * 8;
        const float* qup = squ[n];
#pragma unroll 4
        for (int d = 0; d < DHH; d++) {
            float qd = qup[d];
            float4 x0 = *(const float4*)&ktp[d * LL];
            float4 x1 = *(const float4*)&ktp[d * LL + 4];
            acck[0] += qd * x0.x; acck[1] += qd * x0.y;
            acck[2] += qd * x0.z; acck[3] += qd * x0.w;
            acck[4] += qd * x1.x; acck[5] += qd * x1.y;
            acck[6] += qd * x1.z; acck[7] += qd * x1.w;
        }
#pragma unroll
        for (int t = 0; t < 8; t++) ss[n][lane * 8 + t] = acck[t];
    }
    __syncthreads();

    // phase 2: B_D — warp w streams rel rows k = w*32 .. w*32+31
    {
        const float* w2p = g_w2 + (size_t)(b * LL + q) * NHH * HH;
        unsigned long long w2u[4][8][2];
#pragma unroll
        for (int j = 0; j < 4; j++) {
#pragma unroll
            for (int n = 0; n < 8; n++) {
                float4 t = *(const float4*)&w2p[n * HH + j * 128 + lane * 4];
                w2u[j][n][0] = pack2(t.x, t.y);
                w2u[j][n][1] = pack2(t.z, t.w);
            }
        }

        const float4* rp = (const float4*)(rel + (size_t)(b * LL + q) * LL * HH);
        int k0 = w * 32;
        float4 cur[4];
#pragma unroll
        for (int j = 0; j < 4; j++) cur[j] = rp[(size_t)k0 * 128 + j * 32 + lane];

        for (int r = 0; r < 32; r++) {
            int k  = k0 + r;
            int kn = (r < 31) ? (k + 1) : k;
            float4 nxt[4];
#pragma unroll
            for (int j = 0; j < 4; j++) nxt[j] = rp[(size_t)kn * 128 + j * 32 + lane];

            unsigned long long p[8];
#pragma unroll
            for (int n = 0; n < 8; n++) p[n] = 0ull;
#pragma unroll
            for (int j = 0; j < 4; j++) {
                unsigned long long rlo = pack2(cur[j].x, cur[j].y);
                unsigned long long rhi = pack2(cur[j].z, cur[j].w);
#pragma unroll
                for (int n = 0; n < 8; n++) {
                    p[n] = fma_f32x2(w2u[j][n][0], rlo, p[n]);
                    p[n] = fma_f32x2(w2u[j][n][1], rhi, p[n]);
                }
            }
            float red[8];
#pragma unroll
            for (int n = 0; n < 8; n++) {
                float2 t = unpack2(p[n]);
                red[n] = t.x + t.y;
            }
#pragma unroll
            for (int s = 16; s > 0; s >>= 1) {
#pragma unroll
                for (int n = 0; n < 8; n++)
                    red[n] += __shfl_xor_sync(0xffffffffu, red[n], s);
            }
            if (lane == 0) {
#pragma unroll
                for (int n = 0; n < 8; n++) ss[n][k] += red[n];
            }
#pragma unroll
            for (int j = 0; j < 4; j++) cur[j] = nxt[j];
        }
    }
    __syncthreads();

    // phase 3: scale + mask + softmax — warp w handles head n=w
    int total = seq_len[b] + lex_num[b];
    {
        int n = w;
        float v[8];
        float4 s0 = *(const float4*)&ss[n][lane * 8];
        float4 s1 = *(const float4*)&ss[n][lane * 8 + 4];
        v[0] = s0.x; v[1] = s0.y; v[2] = s0.z; v[3] = s0.w;
        v[4] = s1.x; v[5] = s1.y; v[6] = s1.z; v[7] = s1.w;
#pragma unroll
        for (int t = 0; t < 8; t++) {
            int kidx = lane * 8 + t;
            v[t] = (kidx < total) ? v[t] * 0.125f : -1e15f;
        }
        float mx = v[0];
#pragma unroll
        for (int t = 1; t < 8; t++) mx = fmaxf(mx, v[t]);
#pragma unroll
        for (int s = 16; s > 0; s >>= 1)
            mx = fmaxf(mx, __shfl_xor_sync(0xffffffffu, mx, s));
        float sum = 0.f;
#pragma unroll
        for (int t = 0; t < 8; t++) { v[t] = expf(v[t] - mx); sum += v[t]; }
#pragma unroll
        for (int s = 16; s > 0; s >>= 1)
            sum += __shfl_xor_sync(0xffffffffu, sum, s);
        float inv = 1.0f / sum;
#pragma unroll
        for (int t = 0; t < 8; t++) v[t] *= inv;
        *(float4*)&ss[n][lane * 8]     = make_float4(v[0], v[1], v[2], v[3]);
        *(float4*)&ss[n][lane * 8 + 4] = make_float4(v[4], v[5], v[6], v[7]);
        __syncwarp();
    }

    // phase 4: attn @ V — warp n, lane owns d = 2*lane, 2*lane+1
    {
        int n = w;
        const float* vp = g_vt + (size_t)(b * NHH + n) * LL * DHH + lane * 2;
        float ax = 0.f, ay = 0.f;
#pragma unroll 4
        for (int k = 0; k < LL; k++) {
            float a = ss[n][k];
            float2 vv = *(const float2*)&vp[k * DHH];
            ax += a * vv.x;
            ay += a * vv.y;
        }
        float* op = g_pre + (size_t)(b * LL + q) * HH + n * DHH + lane * 2;
        op[0] = ax;
        op[1] = ay;
    }
}

// ---------------- launch ----------------
extern "C" void kernel_launch(void* const* d_in, const int* in_sizes, int n_in,
                              void* d_out, int out_size) {
    (void)in_sizes; (void)n_in; (void)out_size;
    const float* key     = (const float*)d_in[0];
    const float* query   = (const float*)d_in[1];
    const float* value   = (const float*)d_in[2];
    const float* rel     = (const float*)d_in[3];
    const float* Wk      = (const float*)d_in[4];
    const float* bk      = (const float*)d_in[5];
    const float* Wq      = (const float*)d_in[6];
    const float* bq      = (const float*)d_in[7];
    const float* Wv      = (const float*)d_in[8];
    const float* bv      = (const float*)d_in[9];
    const float* Wr      = (const float*)d_in[10];
    // d_in[11] = br: additive constant per (b,n,q) row of scores -> cancels in softmax
    const float* u_bias  = (const float*)d_in[12];
    const float* v_bias  = (const float*)d_in[13];
    const float* Wf      = (const float*)d_in[14];
    const float* bf      = (const float*)d_in[15];
    const int*   seq_len = (const int*)d_in[16];
    const int*   lex_num = (const int*)d_in[17];
    float* out = (float*)d_out;

    dim3 g1(8, 8, 3);
    gemm_nt_kernel<<<g1, 256>>>(0, key, query, value, Wk, bk, Wq, bq, Wv, bv, Wf, bf, out);

    dim3 g2(8, 8, NHH);
    w2_kernel<<<g2, 256>>>(Wr, v_bias);

    dim3 g3(LL, BB);
    attn_kernel<<<g3, 256>>>(rel, u_bias, seq_len, lex_num);

    dim3 g4(8, 8, 1);
    gemm_nt_kernel<<<g4, 256>>>(3, key, query, value, Wk, bk, Wq, bq, Wv, bv, Wf, bf, out);
}

// round 4
// speedup vs baseline: 1.7863x; 1.7863x over previous
#include <cuda_runtime.h>
#include <cstdint>
#include <math.h>

typedef unsigned long long u64;

#define BB 2
#define LL 256
#define HH 512
#define NHH 8
#define DHH 64

// ---------------- device scratch ----------------
__device__ float g_qt  [BB*NHH*LL*DHH];   // [b,n,l,d]
__device__ float g_kt  [BB*NHH*LL*DHH];   // [b,n,l,d]
__device__ float g_vt  [BB*NHH*LL*DHH];   // [b,n,l,d]
__device__ float g_w2  [BB*LL*NHH*HH];    // [b,q,n,h]
__device__ float g_ac  [BB*NHH*LL*LL];    // [b,n,q,k]
__device__ float g_attn[BB*NHH*LL*LL];    // [b,n,q,k]
__device__ float g_pre [BB*LL*HH];        // [b,q, n*64+d]

// ---------------- helpers ----------------
__device__ __forceinline__ u64 fma2(u64 a, u64 b, u64 c) {
    u64 d; asm("fma.rn.f32x2 %0, %1, %2, %3;" : "=l"(d) : "l"(a), "l"(b), "l"(c)); return d;
}
__device__ __forceinline__ u64 pack2(float x, float y) {
    u64 r; asm("mov.b64 %0, {%1, %2};" : "=l"(r) : "f"(x), "f"(y)); return r;
}
__device__ __forceinline__ float2 unpack2(u64 v) {
    float2 r; asm("mov.b64 {%0, %1}, %2;" : "=f"(r.x), "=f"(r.y) : "l"(v)); return r;
}

#define CP_ASYNC16(dst, src) asm volatile("cp.async.cg.shared.global [%0], [%1], 16;" :: "r"(dst), "l"(src))
#define CP_COMMIT()          asm volatile("cp.async.commit_group;")
#define CP_WAIT3()           asm volatile("cp.async.wait_group 3;")

// ---------------- shared 64x64 mma inner (32-k step) ----------------
__device__ __forceinline__ void mma32(const float (*As)[68], const float (*Bs)[68],
                                      int ty4, int tx4, u64 acc[2][4]) {
#pragma unroll
    for (int kk = 0; kk < 32; kk++) {
        ulonglong2 a2 = *(const ulonglong2*)&As[kk][ty4];
        float4 bv = *(const float4*)&Bs[kk][tx4];
        u64 b0 = pack2(bv.x, bv.x), b1 = pack2(bv.y, bv.y);
        u64 b2 = pack2(bv.z, bv.z), b3 = pack2(bv.w, bv.w);
        acc[0][0] = fma2(a2.x, b0, acc[0][0]); acc[1][0] = fma2(a2.y, b0, acc[1][0]);
        acc[0][1] = fma2(a2.x, b1, acc[0][1]); acc[1][1] = fma2(a2.y, b1, acc[1][1]);
        acc[0][2] = fma2(a2.x, b2, acc[0][2]); acc[1][2] = fma2(a2.y, b2, acc[1][2]);
        acc[0][3] = fma2(a2.x, b3, acc[0][3]); acc[1][3] = fma2(a2.y, b3, acc[1][3]);
    }
}

#define STS8A(buf, v0, v1) { \
    As[buf][lk+0][lrow]=v0.x; As[buf][lk+1][lrow]=v0.y; As[buf][lk+2][lrow]=v0.z; As[buf][lk+3][lrow]=v0.w; \
    As[buf][lk+4][lrow]=v1.x; As[buf][lk+5][lrow]=v1.y; As[buf][lk+6][lrow]=v1.z; As[buf][lk+7][lrow]=v1.w; }
#define STS8B(buf, v0, v1) { \
    Bs[buf][lk+0][lrow]=v0.x; Bs[buf][lk+1][lrow]=v0.y; Bs[buf][lk+2][lrow]=v0.z; Bs[buf][lk+3][lrow]=v0.w; \
    Bs[buf][lk+4][lrow]=v1.x; Bs[buf][lk+5][lrow]=v1.y; Bs[buf][lk+6][lrow]=v1.z; Bs[buf][lk+7][lrow]=v1.w; }

// ---------------- QKV projection NT GEMM, grid (8,8,3) ----------------
__global__ __launch_bounds__(256, 2) void qkv_kernel(
    const float* __restrict__ query, const float* __restrict__ key, const float* __restrict__ value,
    const float* __restrict__ Wq, const float* __restrict__ bq,
    const float* __restrict__ Wk, const float* __restrict__ bk,
    const float* __restrict__ Wv, const float* __restrict__ bv)
{
    int z = blockIdx.z;
    const float* X    = (z == 0) ? query : (z == 1) ? key : value;
    const float* W    = (z == 0) ? Wq    : (z == 1) ? Wk  : Wv;
    const float* bias = (z == 0) ? bq    : (z == 1) ? bk  : bv;

    __shared__ __align__(16) float As[2][32][68];
    __shared__ __align__(16) float Bs[2][32][68];

    int tid = threadIdx.x;
    int m0 = blockIdx.y * 64, n0 = blockIdx.x * 64;
    int lrow = tid >> 2, lk = (tid & 3) * 8;
    int ty4 = (tid >> 4) * 4, tx4 = (tid & 15) * 4;

    const float* Arow = X + (m0 + lrow) * HH + lk;
    const float* Brow = W + (n0 + lrow) * HH + lk;
    float4 ra0 = *(const float4*)(Arow),     ra1 = *(const float4*)(Arow + 4);
    float4 rb0 = *(const float4*)(Brow),     rb1 = *(const float4*)(Brow + 4);

    u64 acc[2][4];
#pragma unroll
    for (int p = 0; p < 2; p++)
#pragma unroll
        for (int j = 0; j < 4; j++) acc[p][j] = 0ull;

#pragma unroll 1
    for (int s = 0; s < 16; s++) {
        int buf = s & 1;
        STS8A(buf, ra0, ra1); STS8B(buf, rb0, rb1);
        __syncthreads();
        if (s + 1 < 16) {
            ra0 = *(const float4*)(Arow + (s+1)*32);  ra1 = *(const float4*)(Arow + (s+1)*32 + 4);
            rb0 = *(const float4*)(Brow + (s+1)*32);  rb1 = *(const float4*)(Brow + (s+1)*32 + 4);
        }
        mma32(As[buf], Bs[buf], ty4, tx4, acc);
        __syncthreads();
    }

#pragma unroll
    for (int p = 0; p < 2; p++)
#pragma unroll
        for (int j = 0; j < 4; j++) {
            float2 t = unpack2(acc[p][j]);
            int c = n0 + tx4 + j;
            float bb = bias[c];
            int n_ = c >> 6, d_ = c & 63;
#pragma unroll
            for (int e = 0; e < 2; e++) {
                int m = m0 + ty4 + 2*p + e;
                int b_ = m >> 8, l_ = m & 255;
                size_t idx = ((size_t)(b_*NHH + n_)*LL + l_)*DHH + d_;
                float v = ((e == 0) ? t.x : t.y) + bb;
                if (z == 0)      g_qt[idx] = v;
                else if (z == 1) g_kt[idx] = v;
                else             g_vt[idx] = v;
            }
        }
}

// ---------------- W2[b,q,n,h] = sum_d (qt+v_bias)*Wr, grid (8,8,8) ----------------
__global__ __launch_bounds__(256) void w2_kernel(const float* __restrict__ Wr,
                                                 const float* __restrict__ v_bias)
{
    int n = blockIdx.z;
    int m0 = blockIdx.y * 64, h0 = blockIdx.x * 64;
    __shared__ float As[16][68];
    __shared__ float Bs[16][68];
    int tid = threadIdx.x;
    int tx = tid & 15, ty = tid >> 4;
    int lrow = tid >> 2, lk4 = (tid & 3) * 4;
    int brow = tid >> 4, bh4 = (tid & 15) * 4;

    float acc[4][4];
#pragma unroll
    for (int i = 0; i < 4; i++)
#pragma unroll
        for (int j = 0; j < 4; j++) acc[i][j] = 0.f;

    for (int ks = 0; ks < DHH; ks += 16) {
        int m = m0 + lrow; int b_ = m >> 8, q_ = m & 255;
        float4 a  = *(const float4*)&g_qt[((b_*NHH + n)*LL + q_)*DHH + ks + lk4];
        float4 vb = *(const float4*)&v_bias[n*DHH + ks + lk4];
        a.x += vb.x; a.y += vb.y; a.z += vb.z; a.w += vb.w;
        As[lk4+0][lrow] = a.x; As[lk4+1][lrow] = a.y;
        As[lk4+2][lrow] = a.z; As[lk4+3][lrow] = a.w;
        float4 wv = *(const float4*)&Wr[(n*DHH + ks + brow)*HH + h0 + bh4];
        *(float4*)&Bs[brow][bh4] = wv;
        __syncthreads();
#pragma unroll
        for (int kk = 0; kk < 16; kk++) {
            float4 av  = *(const float4*)&As[kk][ty*4];
            float4 bv4 = *(const float4*)&Bs[kk][tx*4];
            acc[0][0] += av.x*bv4.x; acc[0][1] += av.x*bv4.y; acc[0][2] += av.x*bv4.z; acc[0][3] += av.x*bv4.w;
            acc[1][0] += av.y*bv4.x; acc[1][1] += av.y*bv4.y; acc[1][2] += av.y*bv4.z; acc[1][3] += av.y*bv4.w;
            acc[2][0] += av.z*bv4.x; acc[2][1] += av.z*bv4.y; acc[2][2] += av.z*bv4.z; acc[2][3] += av.z*bv4.w;
            acc[3][0] += av.w*bv4.x; acc[3][1] += av.w*bv4.y; acc[3][2] += av.w*bv4.z; acc[3][3] += av.w*bv4.w;
        }
        __syncthreads();
    }
#pragma unroll
    for (int i = 0; i < 4; i++)
#pragma unroll
        for (int j = 0; j < 4; j++) {
            int m = m0 + ty*4 + i, h = h0 + tx*4 + j;
            int b_ = m >> 8, q_ = m & 255;
            g_w2[((size_t)(b_*LL + q_)*NHH + n)*HH + h] = acc[i][j];
        }
}

// ---------------- A_C GEMM: g_ac[bn,q,k] = (qt+u) @ kt^T, grid (4,4,16) ----------------
__global__ __launch_bounds__(256, 2) void ac_kernel(const float* __restrict__ u_bias)
{
    int bn = blockIdx.z;
    int q0 = blockIdx.y * 64, k0 = blockIdx.x * 64;
    int n = bn & 7;

    __shared__ __align__(16) float As[2][32][68];
    __shared__ __align__(16) float Bs[2][32][68];

    int tid = threadIdx.x;
    int lrow = tid >> 2, lk = (tid & 3) * 8;
    int ty4 = (tid >> 4) * 4, tx4 = (tid & 15) * 4;

    const float* Arow = g_qt + ((size_t)bn*LL + q0 + lrow)*DHH + lk;
    const float* Brow = g_kt + ((size_t)bn*LL + k0 + lrow)*DHH + lk;
    const float* Urow = u_bias + n*DHH + lk;

    float4 ra0 = *(const float4*)(Arow),  ra1 = *(const float4*)(Arow + 4);
    float4 u0  = *(const float4*)(Urow),  u1  = *(const float4*)(Urow + 4);
    ra0.x += u0.x; ra0.y += u0.y; ra0.z += u0.z; ra0.w += u0.w;
    ra1.x += u1.x; ra1.y += u1.y; ra1.z += u1.z; ra1.w += u1.w;
    float4 rb0 = *(const float4*)(Brow),  rb1 = *(const float4*)(Brow + 4);

    u64 acc[2][4];
#pragma unroll
    for (int p = 0; p < 2; p++)
#pragma unroll
        for (int j = 0; j < 4; j++) acc[p][j] = 0ull;

#pragma unroll 1
    for (int s = 0; s < 2; s++) {
        int buf = s & 1;
        STS8A(buf, ra0, ra1); STS8B(buf, rb0, rb1);
        __syncthreads();
        if (s == 0) {
            ra0 = *(const float4*)(Arow + 32); ra1 = *(const float4*)(Arow + 36);
            float4 w0 = *(const float4*)(Urow + 32), w1 = *(const float4*)(Urow + 36);
            ra0.x += w0.x; ra0.y += w0.y; ra0.z += w0.z; ra0.w += w0.w;
            ra1.x += w1.x; ra1.y += w1.y; ra1.z += w1.z; ra1.w += w1.w;
            rb0 = *(const float4*)(Brow + 32); rb1 = *(const float4*)(Brow + 36);
        }
        mma32(As[buf], Bs[buf], ty4, tx4, acc);
        __syncthreads();
    }

#pragma unroll
    for (int p = 0; p < 2; p++) {
        float2 t0 = unpack2(acc[p][0]), t1 = unpack2(acc[p][1]);
        float2 t2 = unpack2(acc[p][2]), t3 = unpack2(acc[p][3]);
        int q = q0 + ty4 + 2*p;
        *(float4*)&g_ac[((size_t)bn*LL + q)  *LL + k0 + tx4] = make_float4(t0.x, t1.x, t2.x, t3.x);
        *(float4*)&g_ac[((size_t)bn*LL + q+1)*LL + k0 + tx4] = make_float4(t0.y, t1.y, t2.y, t3.y);
    }
}

// ---------------- B_D + softmax, grid (256,2), 64KB dynamic smem ring ----------------
__global__ __launch_bounds__(256, 1) void bd_kernel(
    const float* __restrict__ rel,
    const int* __restrict__ seq_len, const int* __restrict__ lex_num)
{
    extern __shared__ __align__(16) float ring[];       // [8 warps][4 slots][512]
    __shared__ __align__(16) float ss[NHH * 260];       // scores, pitch 260

    int q = blockIdx.x, b = blockIdx.y;
    int tid = threadIdx.x, w = tid >> 5, lane = tid & 31;

    // preload A_C: warp w owns head w
    {
        const float* acp = g_ac + ((size_t)(b*NHH + w)*LL + q)*LL;
        *(float4*)&ss[w*260 + lane*8]     = *(const float4*)&acp[lane*8];
        *(float4*)&ss[w*260 + lane*8 + 4] = *(const float4*)&acp[lane*8 + 4];
    }

    // w2 into registers (lane owns h = j*128 + lane*4 .. +3, all 8 heads)
    const float* w2p = g_w2 + (size_t)(b*LL + q)*NHH*HH;
    ulonglong2 w2u[4][8];
#pragma unroll
    for (int j = 0; j < 4; j++)
#pragma unroll
        for (int n = 0; n < 8; n++)
            w2u[j][n] = *(const ulonglong2*)&w2p[n*HH + j*128 + lane*4];

    const float* relrow = rel + (((size_t)(b*LL + q))*LL + w*32)*HH + lane*4;
    float* myring = ring + w*4*HH;
    uint32_t rbase = (uint32_t)__cvta_generic_to_shared(myring) + lane*16;

#define ISSUE_ROW(row, slot) { const float* s_ = relrow + (size_t)(row)*HH; uint32_t d_ = rbase + (slot)*2048; \
    CP_ASYNC16(d_,      s_);       CP_ASYNC16(d_+512,  s_+128); \
    CP_ASYNC16(d_+1024, s_+256);   CP_ASYNC16(d_+1536, s_+384); }

    ISSUE_ROW(0, 0); CP_COMMIT();
    ISSUE_ROW(1, 1); CP_COMMIT();
    ISSUE_ROW(2, 2); CP_COMMIT();
    __syncthreads();   // A_C preload visible to all warps

#pragma unroll 1
    for (int r = 0; r < 32; r++) {
        if (r + 3 < 32) { ISSUE_ROW(r+3, (r+3)&3); }
        CP_COMMIT();
        CP_WAIT3();
        const float* slot = myring + (r & 3)*HH;
        u64 p[8];
#pragma unroll
        for (int n = 0; n < 8; n++) p[n] = 0ull;
#pragma unroll
        for (int j = 0; j < 4; j++) {
            ulonglong2 rv = *(const ulonglong2*)&slot[j*128 + lane*4];
#pragma unroll
            for (int n = 0; n < 8; n++) {
                p[n] = fma2(w2u[j][n].x, rv.x, p[n]);
                p[n] = fma2(w2u[j][n].y, rv.y, p[n]);
            }
        }
        float s[8];
#pragma unroll
        for (int n = 0; n < 8; n++) { float2 t = unpack2(p[n]); s[n] = t.x + t.y; }
        // multi-value butterfly: 9 SHFLs, head n lands on lanes 4n..4n+3
        bool h16 = (lane & 16) != 0;
        float a[4];
#pragma unroll
        for (int i = 0; i < 4; i++) {
            float keep = h16 ? s[i+4] : s[i];
            float send = h16 ? s[i]   : s[i+4];
            a[i] = keep + __shfl_xor_sync(0xffffffffu, send, 16);
        }
        bool h8 = (lane & 8) != 0;
        float c[2];
#pragma unroll
        for (int i = 0; i < 2; i++) {
            float keep = h8 ? a[i+2] : a[i];
            float send = h8 ? a[i]   : a[i+2];
            c[i] = keep + __shfl_xor_sync(0xffffffffu, send, 8);
        }
        bool h4 = (lane & 4) != 0;
        float keep = h4 ? c[1] : c[0];
        float send = h4 ? c[0] : c[1];
        float e = keep + __shfl_xor_sync(0xffffffffu, send, 4);
        e += __shfl_xor_sync(0xffffffffu, e, 2);
        e += __shfl_xor_sync(0xffffffffu, e, 1);
        if ((lane & 3) == 0)
            ss[(lane >> 2)*260 + w*32 + r] += e;
    }
    __syncthreads();

    // softmax head w + write attn
    int total = seq_len[b] + lex_num[b];
    {
        float v[8];
        float4 s0 = *(const float4*)&ss[w*260 + lane*8];
        float4 s1 = *(const float4*)&ss[w*260 + lane*8 + 4];
        v[0]=s0.x; v[1]=s0.y; v[2]=s0.z; v[3]=s0.w;
        v[4]=s1.x; v[5]=s1.y; v[6]=s1.z; v[7]=s1.w;
#pragma unroll
        for (int t = 0; t < 8; t++) {
            int kidx = lane*8 + t;
            v[t] = (kidx < total) ? v[t] * 0.125f : -1e15f;
        }
        float mx = v[0];
#pragma unroll
        for (int t = 1; t < 8; t++) mx = fmaxf(mx, v[t]);
#pragma unroll
        for (int sft = 16; sft > 0; sft >>= 1) mx = fmaxf(mx, __shfl_xor_sync(0xffffffffu, mx, sft));
        float sum = 0.f;
#pragma unroll
        for (int t = 0; t < 8; t++) { v[t] = expf(v[t] - mx); sum += v[t]; }
#pragma unroll
        for (int sft = 16; sft > 0; sft >>= 1) sum += __shfl_xor_sync(0xffffffffu, sum, sft);
        float inv = 1.0f / sum;
#pragma unroll
        for (int t = 0; t < 8; t++) v[t] *= inv;
        float* op = g_attn + ((size_t)(b*NHH + w)*LL + q)*LL + lane*8;
        *(float4*)(op)     = make_float4(v[0], v[1], v[2], v[3]);
        *(float4*)(op + 4) = make_float4(v[4], v[5], v[6], v[7]);
    }
}

// ---------------- AV GEMM (NN): g_pre = attn @ v, grid (4,16) ----------------
__global__ __launch_bounds__(256, 2) void av_kernel()
{
    int q0 = blockIdx.x * 64, bn = blockIdx.y;
    int b = bn >> 3, n = bn & 7;

    __shared__ __align__(16) float As[2][32][68];
    __shared__ __align__(16) float Bs[2][32][68];

    int tid = threadIdx.x;
    int lrow = tid >> 2, lk = (tid & 3) * 8;        // A loader (transpose)
    int brow = tid >> 3, bcol = (tid & 7) * 8;      // B loader (direct), 32 rows x 64 cols
    int ty4 = (tid >> 4) * 4, tx4 = (tid & 15) * 4;

    const float* Arow = g_attn + ((size_t)bn*LL + q0 + lrow)*LL + lk;
    const float* Brow = g_vt   + (size_t)bn*LL*DHH + brow*DHH + bcol;

    float4 ra0 = *(const float4*)(Arow),  ra1 = *(const float4*)(Arow + 4);
    float4 rb0 = *(const float4*)(Brow),  rb1 = *(const float4*)(Brow + 4);

    u64 acc[2][4];
#pragma unroll
    for (int p = 0; p < 2; p++)
#pragma unroll
        for (int j = 0; j < 4; j++) acc[p][j] = 0ull;

#pragma unroll 1
    for (int s = 0; s < 8; s++) {
        int buf = s & 1;
        STS8A(buf, ra0, ra1);
        *(float4*)&Bs[buf][brow][bcol]     = rb0;
        *(float4*)&Bs[buf][brow][bcol + 4] = rb1;
        __syncthreads();
        if (s + 1 < 8) {
            ra0 = *(const float4*)(Arow + (s+1)*32);            ra1 = *(const float4*)(Arow + (s+1)*32 + 4);
            rb0 = *(const float4*)(Brow + (s+1)*32*DHH);        rb1 = *(const float4*)(Brow + (s+1)*32*DHH + 4);
        }
        mma32(As[buf], Bs[buf], ty4, tx4, acc);
        __syncthreads();
    }

#pragma unroll
    for (int p = 0; p < 2; p++)
#pragma unroll
        for (int j = 0; j < 4; j++) {
            float2 t = unpack2(acc[p][j]);
            int d = tx4 + j;
            int q = q0 + ty4 + 2*p;
            g_pre[((size_t)(b*LL + q))    *HH + n*DHH + d] = t.x;
            g_pre[((size_t)(b*LL + q + 1))*HH + n*DHH + d] = t.y;
        }
}

// ---------------- final NT GEMM: out = g_pre @ Wf^T + bf, grid (8,8) ----------------
__global__ __launch_bounds__(256, 2) void wf_kernel(const float* __restrict__ Wf,
                                                    const float* __restrict__ bf,
                                                    float* __restrict__ out)
{
    __shared__ __align__(16) float As[2][32][68];
    __shared__ __align__(16) float Bs[2][32][68];

    int tid = threadIdx.x;
    int m0 = blockIdx.y * 64, n0 = blockIdx.x * 64;
    int lrow = tid >> 2, lk = (tid & 3) * 8;
    int ty4 = (tid >> 4) * 4, tx4 = (tid & 15) * 4;

    const float* Arow = g_pre + (m0 + lrow)*HH + lk;
    const float* Brow = Wf    + (n0 + lrow)*HH + lk;
    float4 ra0 = *(const float4*)(Arow),  ra1 = *(const float4*)(Arow + 4);
    float4 rb0 = *(const float4*)(Brow),  rb1 = *(const float4*)(Brow + 4);

    u64 acc[2][4];
#pragma unroll
    for (int p = 0; p < 2; p++)
#pragma unroll
        for (int j = 0; j < 4; j++) acc[p][j] = 0ull;

#pragma unroll 1
    for (int s = 0; s < 16; s++) {
        int buf = s & 1;
        STS8A(buf, ra0, ra1); STS8B(buf, rb0, rb1);
        __syncthreads();
        if (s + 1 < 16) {
            ra0 = *(const float4*)(Arow + (s+1)*32);  ra1 = *(const float4*)(Arow + (s+1)*32 + 4);
            rb0 = *(const float4*)(Brow + (s+1)*32);  rb1 = *(const float4*)(Brow + (s+1)*32 + 4);
        }
        mma32(As[buf], Bs[buf], ty4, tx4, acc);
        __syncthreads();
    }

#pragma unroll
    for (int p = 0; p < 2; p++)
#pragma unroll
        for (int j = 0; j < 4; j++) {
            float2 t = unpack2(acc[p][j]);
            int c = n0 + tx4 + j;
            float bb = bf[c];
            int m = m0 + ty4 + 2*p;
            out[(size_t)m*HH + c]     = t.x + bb;
            out[(size_t)(m+1)*HH + c] = t.y + bb;
        }
}

// ---------------- launch ----------------
extern "C" void kernel_launch(void* const* d_in, const int* in_sizes, int n_in,
                              void* d_out, int out_size) {
    (void)in_sizes; (void)n_in; (void)out_size;
    const float* key     = (const float*)d_in[0];
    const float* query   = (const float*)d_in[1];
    const float* value   = (const float*)d_in[2];
    const float* rel     = (const float*)d_in[3];
    const float* Wk      = (const float*)d_in[4];
    const float* bk      = (const float*)d_in[5];
    const float* Wq      = (const float*)d_in[6];
    const float* bq      = (const float*)d_in[7];
    const float* Wv      = (const float*)d_in[8];
    const float* bv      = (const float*)d_in[9];
    const float* Wr      = (const float*)d_in[10];
    // d_in[11] = br: constant per score row -> cancels in softmax
    const float* u_bias  = (const float*)d_in[12];
    const float* v_bias  = (const float*)d_in[13];
    const float* Wf      = (const float*)d_in[14];
    const float* bf      = (const float*)d_in[15];
    const int*   seq_len = (const int*)d_in[16];
    const int*   lex_num = (const int*)d_in[17];
    float* out = (float*)d_out;

    cudaFuncSetAttribute(bd_kernel, cudaFuncAttributeMaxDynamicSharedMemorySize, 65536);

    qkv_kernel<<<dim3(8, 8, 3), 256>>>(query, key, value, Wq, bq, Wk, bk, Wv, bv);
    w2_kernel<<<dim3(8, 8, NHH), 256>>>(Wr, v_bias);
    ac_kernel<<<dim3(4, 4, 16), 256>>>(u_bias);
    bd_kernel<<<dim3(LL, BB), 256, 65536>>>(rel, seq_len, lex_num);
    av_kernel<<<dim3(4, 16), 256>>>();
    wf_kernel<<<dim3(8, 8), 256>>>(Wf, bf, out);
}